// round 1
// baseline (speedup 1.0000x reference)
#include <cuda_runtime.h>
#include <math.h>

// Problem shape (fixed by the dataset)
#define BATCH 4
#define SEQ   2048
#define CH    1024
#define HALF  (CH/2)

// GEMM tiling
#define BM 128
#define BN 128
#define BK 8
#define TM 8
#define TN 8

// ---------------------------------------------------------------------------
// Static device scratch (no cudaMalloc allowed)
// ---------------------------------------------------------------------------
__device__ float g_Q [(size_t)BATCH * SEQ * CH];
__device__ float g_K [(size_t)BATCH * SEQ * CH];
__device__ float g_V [(size_t)BATCH * SEQ * CH];
__device__ float g_AO[(size_t)BATCH * SEQ * CH];
__device__ float g_S [(size_t)BATCH * SEQ * SEQ];   // scores / probabilities
__device__ float g_cos[SEQ * HALF];
__device__ float g_sin[SEQ * HALF];

// ---------------------------------------------------------------------------
// RoPE cos/sin table — mimic the fp32 reference pipeline exactly:
// inv_freq = 1 / theta^{(2i)/C} in fp32, angle = t * inv_freq in fp32.
// ---------------------------------------------------------------------------
__global__ void rope_table_kernel() {
    int idx = blockIdx.x * blockDim.x + threadIdx.x;
    if (idx >= SEQ * HALF) return;
    int t = idx / HALF;
    int i = idx - t * HALF;
    float expo = (float)(2 * i) / (float)CH;      // exact in fp32
    float inv  = 1.0f / powf(10000.0f, expo);
    float ang  = (float)t * inv;
    g_cos[idx] = cosf(ang);
    g_sin[idx] = sinf(ang);
}

// ---------------------------------------------------------------------------
// Generic NN SGEMM: C = A[M,K] @ B[K,N] (+bias) with optional RoPE epilogue
// and optional causal K-limit (for P@V). Batched via blockIdx.z strides.
// All dims are multiples of the tile sizes — no bounds checks.
// ---------------------------------------------------------------------------
template<bool ROPE, bool CAUSALK, bool HASBIAS>
__global__ void __launch_bounds__(256)
sgemm_nn(const float* __restrict__ A, const float* __restrict__ Bm,
         const float* __restrict__ bias, float* __restrict__ C,
         int K, int N,
         size_t sA, size_t sB, size_t sC)
{
    const int tid  = threadIdx.x;
    const int brow = blockIdx.y, bcol = blockIdx.x;

    const float* Ab = A + (size_t)blockIdx.z * sA + (size_t)brow * BM * K;
    const float* Bb = Bm + (size_t)blockIdx.z * sB + (size_t)bcol * BN;
    float*       Cb = C + (size_t)blockIdx.z * sC;

    __shared__ float As[BK][BM];
    __shared__ float Bs[BK][BN];

    const int arow = tid >> 1;          // 0..127
    const int acol = (tid & 1) * 4;     // 0 or 4
    const int brw  = tid >> 5;          // 0..7
    const int bcl  = (tid & 31) * 4;    // 0..124
    const int tr   = (tid >> 4) * TM;   // 0..120
    const int tc   = (tid & 15) * TN;   // 0..120

    float acc[TM][TN];
    #pragma unroll
    for (int i = 0; i < TM; i++)
        #pragma unroll
        for (int j = 0; j < TN; j++) acc[i][j] = 0.0f;

    const int kend = CAUSALK ? ((brow + 1) * BM < K ? (brow + 1) * BM : K) : K;

    for (int k0 = 0; k0 < kend; k0 += BK) {
        float4 a = *(const float4*)(Ab + (size_t)arow * K + (k0 + acol));
        As[acol + 0][arow] = a.x;
        As[acol + 1][arow] = a.y;
        As[acol + 2][arow] = a.z;
        As[acol + 3][arow] = a.w;
        *(float4*)&Bs[brw][bcl] = *(const float4*)(Bb + (size_t)(k0 + brw) * N + bcl);
        __syncthreads();
        #pragma unroll
        for (int k = 0; k < BK; k++) {
            float4 a0 = *(const float4*)&As[k][tr];
            float4 a1 = *(const float4*)&As[k][tr + 4];
            float4 b0 = *(const float4*)&Bs[k][tc];
            float4 b1 = *(const float4*)&Bs[k][tc + 4];
            float ra[TM] = {a0.x, a0.y, a0.z, a0.w, a1.x, a1.y, a1.z, a1.w};
            float rb[TN] = {b0.x, b0.y, b0.z, b0.w, b1.x, b1.y, b1.z, b1.w};
            #pragma unroll
            for (int i = 0; i < TM; i++)
                #pragma unroll
                for (int j = 0; j < TN; j++)
                    acc[i][j] = fmaf(ra[i], rb[j], acc[i][j]);
        }
        __syncthreads();
    }

    const int grow0 = brow * BM + tr;
    const int gcol0 = bcol * BN + tc;
    #pragma unroll
    for (int i = 0; i < TM; i++) {
        int r = grow0 + i;
        float* Crow = Cb + (size_t)r * N;
        if (ROPE) {
            int t = r & (SEQ - 1);   // row within batch
            #pragma unroll
            for (int j = 0; j < TN; j += 2) {
                int n = gcol0 + j;
                float v0 = acc[i][j]     + (HASBIAS ? bias[n]     : 0.0f);
                float v1 = acc[i][j + 1] + (HASBIAS ? bias[n + 1] : 0.0f);
                int pi = n >> 1;
                float cth = g_cos[t * HALF + pi];
                float sth = g_sin[t * HALF + pi];
                Crow[n]     = v0 * cth - v1 * sth;
                Crow[n + 1] = v1 * cth + v0 * sth;
            }
        } else {
            #pragma unroll
            for (int j = 0; j < TN; j++) {
                int n = gcol0 + j;
                Crow[n] = acc[i][j] + (HASBIAS ? bias[n] : 0.0f);
            }
        }
    }
}

// ---------------------------------------------------------------------------
// QK^T (NT GEMM) with causal mask and 1/sqrt(C) scale. Fully-masked tiles
// short-circuit (skip ~half the FLOPs).
// ---------------------------------------------------------------------------
__global__ void __launch_bounds__(256)
qk_kernel()
{
    const int b    = blockIdx.z;
    const int brow = blockIdx.y, bcol = blockIdx.x;
    const int tid  = threadIdx.x;
    const int tr   = (tid >> 4) * TM;
    const int tc   = (tid & 15) * TN;
    const int grow0 = brow * BM + tr;   // query index t (within batch)
    const int gcol0 = bcol * BN + tc;   // key index s

    float* Sb = g_S + (size_t)b * SEQ * SEQ;

    if (bcol > brow) {   // tile entirely above diagonal
        #pragma unroll
        for (int i = 0; i < TM; i++) {
            float* Srow = Sb + (size_t)(grow0 + i) * SEQ;
            #pragma unroll
            for (int j = 0; j < TN; j++) Srow[gcol0 + j] = -INFINITY;
        }
        return;
    }

    const float* Qb = g_Q + (size_t)b * SEQ * CH + (size_t)brow * BM * CH;
    const float* Kb = g_K + (size_t)b * SEQ * CH + (size_t)bcol * BN * CH;

    __shared__ float As[BK][BM];
    __shared__ float Bs[BK][BN];
    const int arow = tid >> 1;
    const int acol = (tid & 1) * 4;

    float acc[TM][TN];
    #pragma unroll
    for (int i = 0; i < TM; i++)
        #pragma unroll
        for (int j = 0; j < TN; j++) acc[i][j] = 0.0f;

    for (int k0 = 0; k0 < CH; k0 += BK) {
        float4 a = *(const float4*)(Qb + (size_t)arow * CH + (k0 + acol));
        As[acol + 0][arow] = a.x;
        As[acol + 1][arow] = a.y;
        As[acol + 2][arow] = a.z;
        As[acol + 3][arow] = a.w;
        float4 kv = *(const float4*)(Kb + (size_t)arow * CH + (k0 + acol));
        Bs[acol + 0][arow] = kv.x;
        Bs[acol + 1][arow] = kv.y;
        Bs[acol + 2][arow] = kv.z;
        Bs[acol + 3][arow] = kv.w;
        __syncthreads();
        #pragma unroll
        for (int k = 0; k < BK; k++) {
            float4 a0 = *(const float4*)&As[k][tr];
            float4 a1 = *(const float4*)&As[k][tr + 4];
            float4 b0 = *(const float4*)&Bs[k][tc];
            float4 b1 = *(const float4*)&Bs[k][tc + 4];
            float ra[TM] = {a0.x, a0.y, a0.z, a0.w, a1.x, a1.y, a1.z, a1.w};
            float rb[TN] = {b0.x, b0.y, b0.z, b0.w, b1.x, b1.y, b1.z, b1.w};
            #pragma unroll
            for (int i = 0; i < TM; i++)
                #pragma unroll
                for (int j = 0; j < TN; j++)
                    acc[i][j] = fmaf(ra[i], rb[j], acc[i][j]);
        }
        __syncthreads();
    }

    const float scale = 0.03125f;   // 1/sqrt(1024) exact
    #pragma unroll
    for (int i = 0; i < TM; i++) {
        int t = grow0 + i;
        float* Srow = Sb + (size_t)t * SEQ;
        #pragma unroll
        for (int j = 0; j < TN; j++) {
            int s = gcol0 + j;
            Srow[s] = (s <= t) ? acc[i][j] * scale : -INFINITY;
        }
    }
}

// ---------------------------------------------------------------------------
// Row softmax over the scores (in place). -inf entries become exact 0,
// so the subsequent PV GEMM needs no masking.
// ---------------------------------------------------------------------------
__global__ void __launch_bounds__(256)
softmax_kernel()
{
    const int b = blockIdx.y, t = blockIdx.x;
    float* row = g_S + ((size_t)b * SEQ + t) * SEQ;
    const int tid = threadIdx.x;
    __shared__ float red[8];

    float m = -INFINITY;
    for (int i = tid; i < SEQ; i += 256) m = fmaxf(m, row[i]);
    #pragma unroll
    for (int o = 16; o; o >>= 1) m = fmaxf(m, __shfl_xor_sync(0xffffffffu, m, o));
    if ((tid & 31) == 0) red[tid >> 5] = m;
    __syncthreads();
    float mb = red[0];
    #pragma unroll
    for (int i = 1; i < 8; i++) mb = fmaxf(mb, red[i]);
    __syncthreads();

    float sum = 0.0f;
    for (int i = tid; i < SEQ; i += 256) {
        float e = __expf(row[i] - mb);   // exp(-inf)=0
        row[i] = e;
        sum += e;
    }
    #pragma unroll
    for (int o = 16; o; o >>= 1) sum += __shfl_xor_sync(0xffffffffu, sum, o);
    if ((tid & 31) == 0) red[tid >> 5] = sum;
    __syncthreads();
    float sb = 0.0f;
    #pragma unroll
    for (int i = 0; i < 8; i++) sb += red[i];
    float inv = 1.0f / sb;
    for (int i = tid; i < SEQ; i += 256) row[i] *= inv;
}

// ---------------------------------------------------------------------------
// Launcher
// ---------------------------------------------------------------------------
extern "C" void kernel_launch(void* const* d_in, const int* in_sizes, int n_in,
                              void* d_out, int out_size)
{
    const float* x  = (const float*)d_in[0];
    const float* Wq = (const float*)d_in[1];
    const float* bq = (const float*)d_in[2];
    const float* Wk = (const float*)d_in[3];
    const float* bk = (const float*)d_in[4];
    const float* Wv = (const float*)d_in[5];
    const float* bv = (const float*)d_in[6];
    const float* Wo = (const float*)d_in[7];
    const float* bo = (const float*)d_in[8];
    float* out = (float*)d_out;

    float *Q, *K, *V, *AO, *S;
    cudaGetSymbolAddress((void**)&Q,  g_Q);
    cudaGetSymbolAddress((void**)&K,  g_K);
    cudaGetSymbolAddress((void**)&V,  g_V);
    cudaGetSymbolAddress((void**)&AO, g_AO);
    cudaGetSymbolAddress((void**)&S,  g_S);

    // 1. RoPE tables
    rope_table_kernel<<<(SEQ * HALF + 255) / 256, 256>>>();

    // 2. Projections (M = BATCH*SEQ = 8192)
    dim3 gproj(CH / BN, (BATCH * SEQ) / BM, 1);   // (8, 64)
    sgemm_nn<true,  false, true><<<gproj, 256>>>(x, Wq, bq, Q, CH, CH, 0, 0, 0);
    sgemm_nn<true,  false, true><<<gproj, 256>>>(x, Wk, bk, K, CH, CH, 0, 0, 0);
    sgemm_nn<false, false, true><<<gproj, 256>>>(x, Wv, bv, V, CH, CH, 0, 0, 0);

    // 3. S = QK^T / sqrt(C), causal masked
    dim3 gqk(SEQ / BN, SEQ / BM, BATCH);          // (16, 16, 4)
    qk_kernel<<<gqk, 256>>>();

    // 4. Row softmax
    dim3 gsm(SEQ, BATCH, 1);
    softmax_kernel<<<gsm, 256>>>();

    // 5. AO = P @ V  (causal K-limit halves the work)
    dim3 gpv(CH / BN, SEQ / BM, BATCH);           // (8, 16, 4)
    sgemm_nn<false, true, false><<<gpv, 256>>>(
        S, V, nullptr, AO, SEQ, CH,
        (size_t)SEQ * SEQ, (size_t)SEQ * CH, (size_t)SEQ * CH);

    // 6. out = AO @ Wo + bo
    sgemm_nn<false, false, true><<<gproj, 256>>>(AO, Wo, bo, out, CH, CH, 0, 0, 0);
}

// round 4
// speedup vs baseline: 1.3914x; 1.3914x over previous
#include <cuda_runtime.h>
#include <cuda_bf16.h>
#include <math.h>
#include <stdint.h>

// Problem shape (fixed by the dataset)
#define BATCH 4
#define SEQ   2048
#define CH    1024
#define HALF  (CH/2)
#define KSPLIT (3*CH)   // 3072 : [Ah*Bh | Ah*Bm | Am*Bh] folded into K
#define KSRC   (2*CH)   // 2048 : A stored as [Ah | Am]

// warp-MMA GEMM tiling
#define MM 128
#define NN 128
#define KK 32
#define ROWB 80                    // padded SMEM row stride (bytes) for 32 bf16
#define TILEB (128*ROWB)           // 10240 bytes per operand tile
#define STAGEB (2*TILEB)           // 20480 per stage (A+B)
#define NKIT (KSPLIT/KK)           // 96

// SIMT GEMM tiling (QK / PV)
#define BM 128
#define BN 128
#define BK 8
#define TM 8
#define TN 8

// ---------------------------------------------------------------------------
// Static device scratch
// ---------------------------------------------------------------------------
__device__ float g_Q [(size_t)BATCH * SEQ * CH];
__device__ float g_K [(size_t)BATCH * SEQ * CH];
__device__ float g_V [(size_t)BATCH * SEQ * CH];
__device__ float g_AO[(size_t)BATCH * SEQ * CH];
__device__ float g_S [(size_t)BATCH * SEQ * SEQ];
__device__ float g_cos[SEQ * HALF];
__device__ float g_sin[SEQ * HALF];
__device__ __nv_bfloat16 g_xs [(size_t)BATCH * SEQ * KSRC];  // [M, 2048] = [xh | xm]
__device__ __nv_bfloat16 g_aos[(size_t)BATCH * SEQ * KSRC];
__device__ __nv_bfloat16 g_wq [(size_t)CH * KSPLIT];          // [N, 3072] = [Wh|Wm|Wh]
__device__ __nv_bfloat16 g_wk [(size_t)CH * KSPLIT];
__device__ __nv_bfloat16 g_wv [(size_t)CH * KSPLIT];
__device__ __nv_bfloat16 g_wo [(size_t)CH * KSPLIT];

// ---------------------------------------------------------------------------
// PTX helpers (sm_100 base target: mma.sync + ldmatrix + cp.async only)
// ---------------------------------------------------------------------------
__device__ __forceinline__ uint32_t smem_u32(const void* p) {
    uint32_t a;
    asm("{ .reg .u64 t; cvta.to.shared.u64 t, %1; cvt.u32.u64 %0, t; }" : "=r"(a) : "l"(p));
    return a;
}
__device__ __forceinline__ void cp16(uint32_t dst, const void* src) {
    asm volatile("cp.async.cg.shared.global [%0], [%1], 16;" :: "r"(dst), "l"(src));
}
__device__ __forceinline__ void cp_commit() {
    asm volatile("cp.async.commit_group;" ::: "memory");
}
template<int N>
__device__ __forceinline__ void cp_wait() {
    asm volatile("cp.async.wait_group %0;" :: "n"(N) : "memory");
}
__device__ __forceinline__ void ldsm4(uint32_t& r0, uint32_t& r1, uint32_t& r2, uint32_t& r3,
                                     uint32_t addr) {
    asm volatile("ldmatrix.sync.aligned.m8n8.x4.shared.b16 {%0,%1,%2,%3}, [%4];"
                 : "=r"(r0), "=r"(r1), "=r"(r2), "=r"(r3) : "r"(addr));
}
__device__ __forceinline__ void mma16816(float* c, const uint32_t* a, const uint32_t* b) {
    asm volatile(
        "mma.sync.aligned.m16n8k16.row.col.f32.bf16.bf16.f32 "
        "{%0,%1,%2,%3}, {%4,%5,%6,%7}, {%8,%9}, {%0,%1,%2,%3};"
        : "+f"(c[0]), "+f"(c[1]), "+f"(c[2]), "+f"(c[3])
        : "r"(a[0]), "r"(a[1]), "r"(a[2]), "r"(a[3]), "r"(b[0]), "r"(b[1]));
}

// ---------------------------------------------------------------------------
// RoPE cos/sin table
// ---------------------------------------------------------------------------
__global__ void rope_table_kernel() {
    int idx = blockIdx.x * blockDim.x + threadIdx.x;
    if (idx >= SEQ * HALF) return;
    int t = idx / HALF;
    int i = idx - t * HALF;
    float expo = (float)(2 * i) / (float)CH;
    float inv  = 1.0f / powf(10000.0f, expo);
    float ang  = (float)t * inv;
    g_cos[idx] = cosf(ang);
    g_sin[idx] = sinf(ang);
}

// ---------------------------------------------------------------------------
// fp32 -> [hi | mid] bf16 split for activations (A operand), [M, 2048]
// ---------------------------------------------------------------------------
__global__ void __launch_bounds__(256)
split_a_kernel(const float* __restrict__ src, __nv_bfloat16* __restrict__ dst) {
    size_t i = (size_t)blockIdx.x * 256 + threadIdx.x;
    float v = src[i];
    size_t m = i >> 10;
    int    k = (int)(i & (CH - 1));
    __nv_bfloat16 h = __float2bfloat16(v);
    __nv_bfloat16 md = __float2bfloat16(v - __bfloat162float(h));
    dst[m * KSRC + k]      = h;
    dst[m * KSRC + CH + k] = md;
}

// W[K,N] -> ws[N, 3072] = [Wh^T | Wm^T | Wh^T]
__global__ void __launch_bounds__(256)
split_w_kernel(const float* __restrict__ W, __nv_bfloat16* __restrict__ ws) {
    __shared__ float t[32][33];
    int k0 = blockIdx.y * 32, n0 = blockIdx.x * 32;
    int tx = threadIdx.x & 31, ty = threadIdx.x >> 5;
    for (int r = ty; r < 32; r += 8)
        t[r][tx] = W[(size_t)(k0 + r) * CH + (n0 + tx)];
    __syncthreads();
    for (int r = ty; r < 32; r += 8) {
        int n = n0 + r, k = k0 + tx;
        float v = t[tx][r];
        __nv_bfloat16 h = __float2bfloat16(v);
        __nv_bfloat16 md = __float2bfloat16(v - __bfloat162float(h));
        size_t base = (size_t)n * KSPLIT;
        ws[base + k]          = h;
        ws[base + CH + k]     = md;
        ws[base + 2 * CH + k] = h;
    }
}

// ---------------------------------------------------------------------------
// Warp-MMA bf16x3 GEMM: out[M,CH] = A'[M,3072] @ W'[3072,CH] (+bias, +RoPE)
// Block 128x128x32, 8 warps, warp tile 32x64, double-buffered cp.async.
// A' col remap: [0,1024)->Ah, [1024,2048)->Ah, [2048,3072)->Am over [Ah|Am].
// ---------------------------------------------------------------------------
template<int ROPE>
__global__ void __launch_bounds__(256)
gemm_mma(const __nv_bfloat16* __restrict__ A2K,
         const __nv_bfloat16* __restrict__ W3K,
         const float* __restrict__ bias,
         float* __restrict__ out)
{
    __shared__ __align__(16) char smem[2 * STAGEB];
    const uint32_t sbase = smem_u32(smem);

    const int tid = threadIdx.x;
    const int wid = tid >> 5;
    const int lid = tid & 31;
    const int m0 = blockIdx.y * MM;
    const int n0 = blockIdx.x * NN;
    const int warp_m = (wid & 3) * 32;      // 0,32,64,96
    const int warp_n = (wid >> 2) * 64;     // 0,64

    // stage loader: 1024 x 16B chunks (A 512 + B 512), 4 per thread
    auto load_stage = [&](int s, int it) {
        const int k0 = it * KK;
        const int kA = (k0 < CH) ? k0 : (k0 - CH);
        const uint32_t sa = sbase + s * STAGEB;
        const uint32_t sb = sa + TILEB;
        #pragma unroll
        for (int j = 0; j < 4; j++) {
            int cid = tid + j * 256;
            if (cid < 512) {
                int row = cid >> 2, c = cid & 3;
                cp16(sa + row * ROWB + c * 16,
                     A2K + (size_t)(m0 + row) * KSRC + kA + c * 8);
            } else {
                int cid2 = cid - 512;
                int row = cid2 >> 2, c = cid2 & 3;
                cp16(sb + row * ROWB + c * 16,
                     W3K + (size_t)(n0 + row) * KSPLIT + k0 + c * 8);
            }
        }
        cp_commit();
    };

    float acc[2][8][4];
    #pragma unroll
    for (int i = 0; i < 2; i++)
        #pragma unroll
        for (int j = 0; j < 8; j++)
            #pragma unroll
            for (int r = 0; r < 4; r++) acc[i][j][r] = 0.0f;

    load_stage(0, 0);

    for (int it = 0; it < NKIT; it++) {
        if (it + 1 < NKIT) { load_stage((it + 1) & 1, it + 1); cp_wait<1>(); }
        else               { cp_wait<0>(); }
        __syncthreads();

        const uint32_t sa = sbase + (it & 1) * STAGEB;
        const uint32_t sb = sa + TILEB;

        #pragma unroll
        for (int ks = 0; ks < 2; ks++) {
            const uint32_t coff = ks * 32 + (lid >> 4) * 16;   // bytes within row
            uint32_t a[2][4], b[4][4];
            #pragma unroll
            for (int mt = 0; mt < 2; mt++)
                ldsm4(a[mt][0], a[mt][1], a[mt][2], a[mt][3],
                      sa + (warp_m + mt * 16 + (lid & 15)) * ROWB + coff);
            #pragma unroll
            for (int nt4 = 0; nt4 < 4; nt4++)
                ldsm4(b[nt4][0], b[nt4][1], b[nt4][2], b[nt4][3],
                      sb + (warp_n + nt4 * 16 + (lid & 15)) * ROWB + coff);
            #pragma unroll
            for (int mt = 0; mt < 2; mt++) {
                #pragma unroll
                for (int nt4 = 0; nt4 < 4; nt4++) {
                    uint32_t b0[2] = {b[nt4][0], b[nt4][2]};
                    uint32_t b1[2] = {b[nt4][1], b[nt4][3]};
                    mma16816(acc[mt][2 * nt4],     a[mt], b0);
                    mma16816(acc[mt][2 * nt4 + 1], a[mt], b1);
                }
            }
        }
        __syncthreads();
    }

    // ---- epilogue: bias + optional RoPE, write fp32 ----
    #pragma unroll
    for (int mt = 0; mt < 2; mt++) {
        const int r0 = m0 + warp_m + mt * 16 + (lid >> 2);
        #pragma unroll
        for (int half = 0; half < 2; half++) {     // c0c1 row r0 ; c2c3 row r0+8
            const int row = r0 + half * 8;
            float* Crow = out + (size_t)row * CH;
            const int t = row & (SEQ - 1);
            #pragma unroll
            for (int nt = 0; nt < 8; nt++) {
                const int n = n0 + warp_n + nt * 8 + 2 * (lid & 3);   // even
                float v0 = acc[mt][nt][2 * half];
                float v1 = acc[mt][nt][2 * half + 1];
                v0 += bias[n];
                v1 += bias[n + 1];
                if (ROPE) {
                    const int pi = n >> 1;
                    float cth = g_cos[t * HALF + pi];
                    float sth = g_sin[t * HALF + pi];
                    float o0 = v0 * cth - v1 * sth;
                    float o1 = v1 * cth + v0 * sth;
                    v0 = o0; v1 = o1;
                }
                *(float2*)(Crow + n) = make_float2(v0, v1);
            }
        }
    }
}

// ---------------------------------------------------------------------------
// SIMT PV GEMM : AO = P @ V with causal K-limit
// ---------------------------------------------------------------------------
template<bool CAUSALK>
__global__ void __launch_bounds__(256)
sgemm_nn(const float* __restrict__ A, const float* __restrict__ Bm,
         float* __restrict__ C, int K, int N,
         size_t sA, size_t sB, size_t sC)
{
    const int tid  = threadIdx.x;
    const int brow = blockIdx.y, bcol = blockIdx.x;
    const float* Ab = A + (size_t)blockIdx.z * sA + (size_t)brow * BM * K;
    const float* Bb = Bm + (size_t)blockIdx.z * sB + (size_t)bcol * BN;
    float*       Cb = C + (size_t)blockIdx.z * sC;

    __shared__ float As[BK][BM];
    __shared__ float Bs[BK][BN];
    const int arow = tid >> 1;
    const int acol = (tid & 1) * 4;
    const int brw  = tid >> 5;
    const int bcl  = (tid & 31) * 4;
    const int tr   = (tid >> 4) * TM;
    const int tc   = (tid & 15) * TN;

    float acc[TM][TN];
    #pragma unroll
    for (int i = 0; i < TM; i++)
        #pragma unroll
        for (int j = 0; j < TN; j++) acc[i][j] = 0.0f;

    const int kend = CAUSALK ? ((brow + 1) * BM < K ? (brow + 1) * BM : K) : K;

    for (int k0 = 0; k0 < kend; k0 += BK) {
        float4 a = *(const float4*)(Ab + (size_t)arow * K + (k0 + acol));
        As[acol + 0][arow] = a.x;
        As[acol + 1][arow] = a.y;
        As[acol + 2][arow] = a.z;
        As[acol + 3][arow] = a.w;
        *(float4*)&Bs[brw][bcl] = *(const float4*)(Bb + (size_t)(k0 + brw) * N + bcl);
        __syncthreads();
        #pragma unroll
        for (int k = 0; k < BK; k++) {
            float4 a0 = *(const float4*)&As[k][tr];
            float4 a1 = *(const float4*)&As[k][tr + 4];
            float4 b0 = *(const float4*)&Bs[k][tc];
            float4 b1 = *(const float4*)&Bs[k][tc + 4];
            float ra[TM] = {a0.x, a0.y, a0.z, a0.w, a1.x, a1.y, a1.z, a1.w};
            float rb[TN] = {b0.x, b0.y, b0.z, b0.w, b1.x, b1.y, b1.z, b1.w};
            #pragma unroll
            for (int i = 0; i < TM; i++)
                #pragma unroll
                for (int j = 0; j < TN; j++)
                    acc[i][j] = fmaf(ra[i], rb[j], acc[i][j]);
        }
        __syncthreads();
    }

    const int grow0 = brow * BM + tr;
    const int gcol0 = bcol * BN + tc;
    #pragma unroll
    for (int i = 0; i < TM; i++) {
        float* Crow = Cb + (size_t)(grow0 + i) * N;
        #pragma unroll
        for (int j = 0; j < TN; j++) Crow[gcol0 + j] = acc[i][j];
    }
}

// ---------------------------------------------------------------------------
// QK^T with causal mask + scale
// ---------------------------------------------------------------------------
__global__ void __launch_bounds__(256)
qk_kernel()
{
    const int b    = blockIdx.z;
    const int brow = blockIdx.y, bcol = blockIdx.x;
    const int tid  = threadIdx.x;
    const int tr   = (tid >> 4) * TM;
    const int tc   = (tid & 15) * TN;
    const int grow0 = brow * BM + tr;
    const int gcol0 = bcol * BN + tc;

    float* Sb = g_S + (size_t)b * SEQ * SEQ;

    if (bcol > brow) {
        #pragma unroll
        for (int i = 0; i < TM; i++) {
            float* Srow = Sb + (size_t)(grow0 + i) * SEQ;
            #pragma unroll
            for (int j = 0; j < TN; j++) Srow[gcol0 + j] = -INFINITY;
        }
        return;
    }

    const float* Qb = g_Q + (size_t)b * SEQ * CH + (size_t)brow * BM * CH;
    const float* Kb = g_K + (size_t)b * SEQ * CH + (size_t)bcol * BN * CH;

    __shared__ float As[BK][BM];
    __shared__ float Bs[BK][BN];
    const int arow = tid >> 1;
    const int acol = (tid & 1) * 4;

    float acc[TM][TN];
    #pragma unroll
    for (int i = 0; i < TM; i++)
        #pragma unroll
        for (int j = 0; j < TN; j++) acc[i][j] = 0.0f;

    for (int k0 = 0; k0 < CH; k0 += BK) {
        float4 a = *(const float4*)(Qb + (size_t)arow * CH + (k0 + acol));
        As[acol + 0][arow] = a.x;
        As[acol + 1][arow] = a.y;
        As[acol + 2][arow] = a.z;
        As[acol + 3][arow] = a.w;
        float4 kv = *(const float4*)(Kb + (size_t)arow * CH + (k0 + acol));
        Bs[acol + 0][arow] = kv.x;
        Bs[acol + 1][arow] = kv.y;
        Bs[acol + 2][arow] = kv.z;
        Bs[acol + 3][arow] = kv.w;
        __syncthreads();
        #pragma unroll
        for (int k = 0; k < BK; k++) {
            float4 a0 = *(const float4*)&As[k][tr];
            float4 a1 = *(const float4*)&As[k][tr + 4];
            float4 b0 = *(const float4*)&Bs[k][tc];
            float4 b1 = *(const float4*)&Bs[k][tc + 4];
            float ra[TM] = {a0.x, a0.y, a0.z, a0.w, a1.x, a1.y, a1.z, a1.w};
            float rb[TN] = {b0.x, b0.y, b0.z, b0.w, b1.x, b1.y, b1.z, b1.w};
            #pragma unroll
            for (int i = 0; i < TM; i++)
                #pragma unroll
                for (int j = 0; j < TN; j++)
                    acc[i][j] = fmaf(ra[i], rb[j], acc[i][j]);
        }
        __syncthreads();
    }

    const float scale = 0.03125f;
    #pragma unroll
    for (int i = 0; i < TM; i++) {
        int t = grow0 + i;
        float* Srow = Sb + (size_t)t * SEQ;
        #pragma unroll
        for (int j = 0; j < TN; j++) {
            int s = gcol0 + j;
            Srow[s] = (s <= t) ? acc[i][j] * scale : -INFINITY;
        }
    }
}

// ---------------------------------------------------------------------------
// Row softmax
// ---------------------------------------------------------------------------
__global__ void __launch_bounds__(256)
softmax_kernel()
{
    const int b = blockIdx.y, t = blockIdx.x;
    float* row = g_S + ((size_t)b * SEQ + t) * SEQ;
    const int tid = threadIdx.x;
    __shared__ float red[8];

    float m = -INFINITY;
    for (int i = tid; i < SEQ; i += 256) m = fmaxf(m, row[i]);
    #pragma unroll
    for (int o = 16; o; o >>= 1) m = fmaxf(m, __shfl_xor_sync(0xffffffffu, m, o));
    if ((tid & 31) == 0) red[tid >> 5] = m;
    __syncthreads();
    float mb = red[0];
    #pragma unroll
    for (int i = 1; i < 8; i++) mb = fmaxf(mb, red[i]);
    __syncthreads();

    float sum = 0.0f;
    for (int i = tid; i < SEQ; i += 256) {
        float e = __expf(row[i] - mb);
        row[i] = e;
        sum += e;
    }
    #pragma unroll
    for (int o = 16; o; o >>= 1) sum += __shfl_xor_sync(0xffffffffu, sum, o);
    if ((tid & 31) == 0) red[tid >> 5] = sum;
    __syncthreads();
    float sb = 0.0f;
    #pragma unroll
    for (int i = 0; i < 8; i++) sb += red[i];
    float inv = 1.0f / sb;
    for (int i = tid; i < SEQ; i += 256) row[i] *= inv;
}

// ---------------------------------------------------------------------------
// Launcher
// ---------------------------------------------------------------------------
extern "C" void kernel_launch(void* const* d_in, const int* in_sizes, int n_in,
                              void* d_out, int out_size)
{
    const float* x  = (const float*)d_in[0];
    const float* Wq = (const float*)d_in[1];
    const float* bq = (const float*)d_in[2];
    const float* Wk = (const float*)d_in[3];
    const float* bk = (const float*)d_in[4];
    const float* Wv = (const float*)d_in[5];
    const float* bv = (const float*)d_in[6];
    const float* Wo = (const float*)d_in[7];
    const float* bo = (const float*)d_in[8];
    float* out = (float*)d_out;

    float *Q, *K, *V, *AO, *S;
    __nv_bfloat16 *xs, *aos, *wq, *wk, *wv, *wo;
    cudaGetSymbolAddress((void**)&Q,   g_Q);
    cudaGetSymbolAddress((void**)&K,   g_K);
    cudaGetSymbolAddress((void**)&V,   g_V);
    cudaGetSymbolAddress((void**)&AO,  g_AO);
    cudaGetSymbolAddress((void**)&S,   g_S);
    cudaGetSymbolAddress((void**)&xs,  g_xs);
    cudaGetSymbolAddress((void**)&aos, g_aos);
    cudaGetSymbolAddress((void**)&wq,  g_wq);
    cudaGetSymbolAddress((void**)&wk,  g_wk);
    cudaGetSymbolAddress((void**)&wv,  g_wv);
    cudaGetSymbolAddress((void**)&wo,  g_wo);

    const size_t M = (size_t)BATCH * SEQ;   // 8192

    // 1. RoPE tables + operand splits
    rope_table_kernel<<<(SEQ * HALF + 255) / 256, 256>>>();
    split_a_kernel<<<(int)(M * CH / 256), 256>>>(x, xs);
    dim3 gw(CH / 32, CH / 32);
    split_w_kernel<<<gw, 256>>>(Wq, wq);
    split_w_kernel<<<gw, 256>>>(Wk, wk);
    split_w_kernel<<<gw, 256>>>(Wv, wv);
    split_w_kernel<<<gw, 256>>>(Wo, wo);

    // 2. Projections on tensor cores (bf16x3, mma.sync)
    dim3 gg(CH / NN, (int)(M / MM));        // (8, 64)
    gemm_mma<1><<<gg, 256>>>(xs, wq, bq, Q);
    gemm_mma<1><<<gg, 256>>>(xs, wk, bk, K);
    gemm_mma<0><<<gg, 256>>>(xs, wv, bv, V);

    // 3. S = QK^T / sqrt(C), causal masked (SIMT)
    dim3 gqk(SEQ / BN, SEQ / BM, BATCH);
    qk_kernel<<<gqk, 256>>>();

    // 4. Row softmax
    dim3 gsm(SEQ, BATCH, 1);
    softmax_kernel<<<gsm, 256>>>();

    // 5. AO = P @ V (SIMT, causal K-limit)
    dim3 gpv(CH / BN, SEQ / BM, BATCH);
    sgemm_nn<true><<<gpv, 256>>>(S, V, AO, SEQ, CH,
        (size_t)SEQ * SEQ, (size_t)SEQ * CH, (size_t)SEQ * CH);

    // 6. out = AO @ Wo + bo (tensor cores)
    split_a_kernel<<<(int)(M * CH / 256), 256>>>(AO, aos);
    gemm_mma<0><<<gg, 256>>>(aos, wo, bo, out);
}